// round 12
// baseline (speedup 1.0000x reference)
#include <cuda_runtime.h>

#define HWSZ (512*512)
#define HR   42            // halo rows
#define HC   37            // halo cols per parity (74 total)
#define NSITE (HR * HC)    // 1554 sites per parity
typedef unsigned long long u64;

__device__ __forceinline__ float ex2f(float x) {
    float r; asm("ex2.approx.f32 %0, %1;" : "=f"(r) : "f"(x)); return r;
}
__device__ __forceinline__ float rcpf(float x) {
    float r; asm("rcp.approx.f32 %0, %1;" : "=f"(r) : "f"(x)); return r;
}
__device__ __forceinline__ u64 pk(float a, float b) {
    u64 r; asm("mov.b64 %0, {%1,%2};" : "=l"(r) : "f"(a), "f"(b)); return r;
}
__device__ __forceinline__ u64 mul2(u64 a, u64 b) {
    u64 r; asm("mul.rn.f32x2 %0, %1, %2;" : "=l"(r) : "l"(a), "l"(b)); return r;
}
__device__ __forceinline__ u64 fma2(u64 a, u64 b, u64 c) {
    u64 r; asm("fma.rn.f32x2 %0, %1, %2, %3;" : "=l"(r) : "l"(a), "l"(b), "l"(c)); return r;
}
__device__ __forceinline__ u64 add2(u64 a, u64 b) {
    u64 r; asm("add.rn.f32x2 %0, %1, %2;" : "=l"(r) : "l"(a), "l"(b)); return r;
}
// round-to-nearest bf16 (high 16 bits of f32)
__device__ __forceinline__ unsigned int bf16_hi(float f) {
    return (__float_as_uint(f) + 0x8000u) >> 16;
}

// Tile 64 wide x 32 tall. Block (32,4)=128 thr. Each thread: 2 adjacent output
// columns (x0+2tx, x0+2tx+1) x 8 rows = 16 px.
// Shared, parity-split (even/odd halo columns in separate dense arrays):
//   A* (16B f32):  (c0,c1,c2,1.0) -> ulonglong2 pairs (c0,c1),(c2,1)
//   B* ( 8B bf16): (u,u4 | u9,u16) -> ALU decode; P5 = mul2(P3,P4)
// Site = 24B -> smem 74.6KB -> 3 blocks/SM (12 warps).
__global__ __launch_bounds__(128, 3) void GaussPSF_kernel(
    const float* __restrict__ img,
    const float* __restrict__ psf,
    float* __restrict__ out)
{
    extern __shared__ char shraw[];
    float4* Ae = reinterpret_cast<float4*>(shraw);
    float4* Ao = Ae + (NSITE + 1);
    uint2*  Be = reinterpret_cast<uint2*>(Ao + (NSITE + 1));
    uint2*  Bo = Be + (NSITE + 1);

    const int tx = threadIdx.x;           // 0..31
    const int ty = threadIdx.y;           // 0..3
    const int tid = ty * 32 + tx;
    const int x0 = blockIdx.x * 64;
    const int y0 = blockIdx.y * 32;
    const int b  = blockIdx.z;

    const float* imb = img + (size_t)b * 3 * HWSZ;
    const float* psb = psf + (size_t)b * HWSZ;

    // ---- stage halo: even+odd pixel pair per iteration ----
    for (int i = tid; i < NSITE; i += 128) {
        int sy = i / HC;
        int sx = i - sy * HC;
        int gy = y0 - 5 + sy;
        #pragma unroll
        for (int par = 0; par < 2; ++par) {
            int gx = x0 - 5 + 2 * sx + par;
            float4 ra;
            uint2  rb;
            if ((unsigned)gy < 512u && (unsigned)gx < 512u) {
                int p = gy * 512 + gx;
                ra.x = imb[p];
                ra.y = imb[HWSZ + p];
                ra.z = imb[2 * HWSZ + p];
                ra.w = 1.0f;
                float w = psb[p];
                float t  = fmaf(w + w, w, 1e-5f);
                float u  = ex2f(-1.4426950408889634f * rcpf(t));
                float u2 = u * u;
                float u4 = u2 * u2;
                float u8 = u4 * u4;
                float u9 = u8 * u;
                float u16 = u8 * u8;
                rb.x = bf16_hi(u)  | (bf16_hi(u4)  << 16);
                rb.y = bf16_hi(u9) | (bf16_hi(u16) << 16);
            } else {
                ra.x = 0.f; ra.y = 0.f; ra.z = 0.f; ra.w = 0.f;
                rb.x = 0u;  rb.y = 0u;
            }
            if (par == 0) { Ae[i] = ra; Be[i] = rb; }
            else          { Ao[i] = ra; Bo[i] = rb; }
        }
    }
    __syncthreads();

    const ulonglong2* Ae64 = reinterpret_cast<const ulonglong2*>(Ae);
    const ulonglong2* Ao64 = reinterpret_cast<const ulonglong2*>(Ao);

    // Accumulators: L = col x0+2tx, R = col x0+2tx+1; 8 rows each
    u64 aL01[8], aL2w[8], aR01[8], aR2w[8];
    #pragma unroll
    for (int o = 0; o < 8; ++o) {
        aL01[o] = 0ull; aL2w[o] = 0ull; aR01[o] = 0ull; aR2w[o] = 0ull;
    }

    const int rowbase = ty * 8;

    #pragma unroll
    for (int s = 0; s < 18; ++s) {
        const int eb = (rowbase + s) * HC + tx;

        #pragma unroll
        for (int m = 0; m < 6; ++m) {
            // ===== EVEN site: halo col 2tx+2m; dxL = 2m-5, dxR = 2m-6 =====
            {
                ulonglong2 av = Ae64[eb + m];
                uint2      bv = Be[eb + m];
                float fu   = __uint_as_float(bv.x << 16);
                float fu4  = __uint_as_float(bv.x & 0xFFFF0000u);
                float fu9  = __uint_as_float(bv.y << 16);
                float fu16 = __uint_as_float(bv.y & 0xFFFF0000u);
                u64 P[6];
                P[1] = pk(fu,   fu);
                P[2] = pk(fu4,  fu4);
                P[3] = pk(fu9,  fu9);
                P[4] = pk(fu16, fu16);
                P[5] = mul2(P[3], P[4]);

                const int aLd = (m < 3) ? (5 - 2 * m) : (2 * m - 5);  // 5,3,1,1,3,5
                const int aRd = (m < 3) ? (6 - 2 * m) : (2 * m - 6);  // 6,4,2,0,2,4
                const bool hasR = (m > 0);

                u64 cL01 = mul2(av.x, P[aLd]);
                u64 cL2w = mul2(av.y, P[aLd]);
                u64 cR01 = 0, cR2w = 0;
                if (hasR) {
                    if (aRd == 0) { cR01 = av.x; cR2w = av.y; }
                    else { cR01 = mul2(av.x, P[aRd]); cR2w = mul2(av.y, P[aRd]); }
                }

                #pragma unroll
                for (int o = 0; o < 8; ++o) {
                    const int dy  = s - 5 - o;
                    const int dya = (dy < 0) ? -dy : dy;
                    if (dya <= 5) {
                        if (dya == 0) {
                            aL01[o] = add2(aL01[o], cL01);
                            aL2w[o] = add2(aL2w[o], cL2w);
                            if (hasR) { aR01[o] = add2(aR01[o], cR01);
                                        aR2w[o] = add2(aR2w[o], cR2w); }
                        } else {
                            aL01[o] = fma2(cL01, P[dya], aL01[o]);
                            aL2w[o] = fma2(cL2w, P[dya], aL2w[o]);
                            if (hasR) { aR01[o] = fma2(cR01, P[dya], aR01[o]);
                                        aR2w[o] = fma2(cR2w, P[dya], aR2w[o]); }
                        }
                    }
                }
            }
            // ===== ODD site: halo col 2tx+2m+1; dxL = 2m-4, dxR = 2m-5 =====
            {
                ulonglong2 av = Ao64[eb + m];
                uint2      bv = Bo[eb + m];
                float fu   = __uint_as_float(bv.x << 16);
                float fu4  = __uint_as_float(bv.x & 0xFFFF0000u);
                float fu9  = __uint_as_float(bv.y << 16);
                float fu16 = __uint_as_float(bv.y & 0xFFFF0000u);
                u64 P[6];
                P[1] = pk(fu,   fu);
                P[2] = pk(fu4,  fu4);
                P[3] = pk(fu9,  fu9);
                P[4] = pk(fu16, fu16);
                P[5] = mul2(P[3], P[4]);

                const int aLd = (m < 2) ? (4 - 2 * m) : (2 * m - 4);  // 4,2,0,2,4,6
                const int aRd = (m < 3) ? (5 - 2 * m) : (2 * m - 5);  // 5,3,1,1,3,5
                const bool hasL = (m < 5);

                u64 cR01 = mul2(av.x, P[aRd]);
                u64 cR2w = mul2(av.y, P[aRd]);
                u64 cL01 = 0, cL2w = 0;
                if (hasL) {
                    if (aLd == 0) { cL01 = av.x; cL2w = av.y; }
                    else { cL01 = mul2(av.x, P[aLd]); cL2w = mul2(av.y, P[aLd]); }
                }

                #pragma unroll
                for (int o = 0; o < 8; ++o) {
                    const int dy  = s - 5 - o;
                    const int dya = (dy < 0) ? -dy : dy;
                    if (dya <= 5) {
                        if (dya == 0) {
                            aR01[o] = add2(aR01[o], cR01);
                            aR2w[o] = add2(aR2w[o], cR2w);
                            if (hasL) { aL01[o] = add2(aL01[o], cL01);
                                        aL2w[o] = add2(aL2w[o], cL2w); }
                        } else {
                            aR01[o] = fma2(cR01, P[dya], aR01[o]);
                            aR2w[o] = fma2(cR2w, P[dya], aR2w[o]);
                            if (hasL) { aL01[o] = fma2(cL01, P[dya], aL01[o]);
                                        aL2w[o] = fma2(cL2w, P[dya], aL2w[o]); }
                        }
                    }
                }
            }
        }
    }

    // ---- normalize & write (float2 stores: columns X, X+1) ----
    float* ob = out + (size_t)b * 3 * HWSZ;
    const int X = x0 + 2 * tx;
    #pragma unroll
    for (int o = 0; o < 8; ++o) {
        float l0, l1, l2, lw, r0, r1, r2, rw;
        asm("mov.b64 {%0,%1}, %2;" : "=f"(l0), "=f"(l1) : "l"(aL01[o]));
        asm("mov.b64 {%0,%1}, %2;" : "=f"(l2), "=f"(lw) : "l"(aL2w[o]));
        asm("mov.b64 {%0,%1}, %2;" : "=f"(r0), "=f"(r1) : "l"(aR01[o]));
        asm("mov.b64 {%0,%1}, %2;" : "=f"(r2), "=f"(rw) : "l"(aR2w[o]));
        float il = rcpf(lw);
        float ir = rcpf(rw);
        int y = y0 + rowbase + o;
        int p = y * 512 + X;
        *reinterpret_cast<float2*>(ob + p)            = make_float2(l0 * il, r0 * ir);
        *reinterpret_cast<float2*>(ob + HWSZ + p)     = make_float2(l1 * il, r1 * ir);
        *reinterpret_cast<float2*>(ob + 2 * HWSZ + p) = make_float2(l2 * il, r2 * ir);
    }
}

extern "C" void kernel_launch(void* const* d_in, const int* in_sizes, int n_in,
                              void* d_out, int out_size)
{
    const float* img = (const float*)d_in[0];   // (4,3,512,512) f32
    const float* psf = (const float*)d_in[1];   // (4,512,512)   f32
    float* out = (float*)d_out;                 // (4,3,512,512) f32

    const int smem = 2 * (NSITE + 1) * 16 + 2 * (NSITE + 1) * 8;   // 74640 B
    cudaFuncSetAttribute(GaussPSF_kernel,
                         cudaFuncAttributeMaxDynamicSharedMemorySize, smem);

    dim3 block(32, 4, 1);
    dim3 grid(512 / 64, 512 / 32, 4);
    GaussPSF_kernel<<<grid, block, smem>>>(img, psf, out);
}

// round 13
// speedup vs baseline: 1.5328x; 1.5328x over previous
#include <cuda_runtime.h>
#include <cuda_fp16.h>

#define HWSZ (512*512)
#define HALO (42*42)
typedef unsigned long long u64;

__device__ __forceinline__ float ex2f(float x) {
    float r; asm("ex2.approx.f32 %0, %1;" : "=f"(r) : "f"(x)); return r;
}
__device__ __forceinline__ float rcpf(float x) {
    float r; asm("rcp.approx.f32 %0, %1;" : "=f"(r) : "f"(x)); return r;
}
__device__ __forceinline__ u64 pk(float a, float b) {
    u64 r; asm("mov.b64 %0, {%1,%2};" : "=l"(r) : "f"(a), "f"(b)); return r;
}
__device__ __forceinline__ u64 add2(u64 a, u64 b) {
    u64 r; asm("add.rn.f32x2 %0, %1, %2;" : "=l"(r) : "l"(a), "l"(b)); return r;
}
__device__ __forceinline__ unsigned int h2u(__half2 h) {
    return *reinterpret_cast<unsigned int*>(&h);
}
__device__ __forceinline__ __half2 u2h(unsigned int u) {
    return *reinterpret_cast<__half2*>(&u);
}

// Tile 32x32 outputs, block (32,4)=128 thr, 8 output rows/thread.
// Site = 16 B (one uint4, one LDS.128):
//   .x = (c0,c1) fp16x2   .y = (c2, 1.0) fp16x2
//   .z = (u, u4) fp16x2   .w = (u9, u16) fp16x2
// Taps in HFMA2 (same rt2 pipe as FFMA2); per-(s,o) fp16 chunk (<=11 taps)
// promoted into f32x2 accumulators once per site-row.
__global__ __launch_bounds__(128, 6) void GaussPSF_kernel(
    const float* __restrict__ img,
    const float* __restrict__ psf,
    float* __restrict__ out)
{
    __shared__ uint4 tile[HALO + 1];      // +1 pad: unconditional prefetch

    const int tx = threadIdx.x;           // 0..31
    const int ty = threadIdx.y;           // 0..3
    const int tid = ty * 32 + tx;
    const int x0 = blockIdx.x * 32;
    const int y0 = blockIdx.y * 32;
    const int b  = blockIdx.z;

    const float* imb = img + (size_t)b * 3 * HWSZ;
    const float* psb = psf + (size_t)b * HWSZ;

    // ---- stage halo: EX2/RCP + power chain once per site; pack fp16 ----
    for (int i = tid; i < HALO; i += 128) {
        int sy = i / 42;
        int sx = i - sy * 42;
        int gy = y0 - 5 + sy;
        int gx = x0 - 5 + sx;
        uint4 r;
        if ((unsigned)gy < 512u && (unsigned)gx < 512u) {
            int p = gy * 512 + gx;
            float c0 = imb[p];
            float c1 = imb[HWSZ + p];
            float c2 = imb[2 * HWSZ + p];
            float w = psb[p];
            float t  = fmaf(w + w, w, 1e-5f);
            float u  = ex2f(-1.4426950408889634f * rcpf(t));
            float u2 = u * u;
            float u4 = u2 * u2;
            float u8 = u4 * u4;
            r.x = h2u(__floats2half2_rn(c0, c1));
            r.y = h2u(__floats2half2_rn(c2, 1.0f));
            r.z = h2u(__floats2half2_rn(u,  u4));
            r.w = h2u(__floats2half2_rn(u8 * u, u8 * u8));  // u9, u16
        } else {
            r.x = 0u; r.y = 0u; r.z = 0u; r.w = 0u;          // mask
        }
        tile[i] = r;
    }
    __syncthreads();

    // ---- 8 outputs per thread: rows y0 + ty*8 + (0..7), column x0 + tx ----
    u64 a01[8], a2w[8];                   // f32x2 master accumulators
    #pragma unroll
    for (int o = 0; o < 8; ++o) { a01[o] = 0ull; a2w[o] = 0ull; }

    const int rowbase = ty * 8;
    const __half2 hz = u2h(0u);

    #pragma unroll
    for (int s = 0; s < 18; ++s) {
        const int base = (rowbase + s) * 42 + tx;
        uint4 bv = tile[base];            // prefetch j=0

        // per-row fp16 chunk accumulators (reset each s; DCE for inactive o)
        __half2 h01[8], h2w[8];
        #pragma unroll
        for (int o = 0; o < 8; ++o) { h01[o] = hz; h2w[o] = hz; }

        #pragma unroll
        for (int j = 0; j < 11; ++j) {
            uint4 nv = tile[base + j + 1];    // unconditional prefetch

            __half2 c01 = u2h(bv.x);
            __half2 c2w = u2h(bv.y);
            __half2 uv  = u2h(bv.z);
            __half2 u916 = u2h(bv.w);

            __half2 D[6];
            D[1] = __low2half2(uv);           // {u,u}
            D[2] = __high2half2(uv);          // {u4,u4}
            D[3] = __low2half2(u916);         // {u9,u9}
            D[4] = __high2half2(u916);        // {u16,u16}
            D[5] = __hmul2(D[3], D[4]);       // {u25,u25}

            const int dxa = (j < 5) ? (5 - j) : (j - 5);
            __half2 m01 = (dxa == 0) ? c01 : __hmul2(c01, D[dxa]);
            __half2 m2w = (dxa == 0) ? c2w : __hmul2(c2w, D[dxa]);

            #pragma unroll
            for (int o = 0; o < 8; ++o) {
                const int dy  = s - 5 - o;     // compile-time after unroll
                const int dya = (dy < 0) ? -dy : dy;
                if (dya <= 5) {
                    if (dya == 0) {
                        h01[o] = __hadd2(h01[o], m01);
                        h2w[o] = __hadd2(h2w[o], m2w);
                    } else {
                        h01[o] = __hfma2(m01, D[dya], h01[o]);
                        h2w[o] = __hfma2(m2w, D[dya], h2w[o]);
                    }
                }
            }
            bv = nv;
        }

        // promote this row's chunks into f32x2 accumulators
        #pragma unroll
        for (int o = 0; o < 8; ++o) {
            const int dy  = s - 5 - o;
            const int dya = (dy < 0) ? -dy : dy;
            if (dya <= 5) {
                float2 f1 = __half22float2(h01[o]);
                float2 f2 = __half22float2(h2w[o]);
                a01[o] = add2(a01[o], pk(f1.x, f1.y));
                a2w[o] = add2(a2w[o], pk(f2.x, f2.y));
            }
        }
    }

    // ---- normalize & write ----
    float* ob = out + (size_t)b * 3 * HWSZ;
    #pragma unroll
    for (int o = 0; o < 8; ++o) {
        float o0, o1, o2, ws;
        asm("mov.b64 {%0,%1}, %2;" : "=f"(o0), "=f"(o1) : "l"(a01[o]));
        asm("mov.b64 {%0,%1}, %2;" : "=f"(o2), "=f"(ws) : "l"(a2w[o]));
        float rw = rcpf(ws);
        int y = y0 + rowbase + o;
        int p = y * 512 + x0 + tx;
        ob[p]            = o0 * rw;
        ob[HWSZ + p]     = o1 * rw;
        ob[2 * HWSZ + p] = o2 * rw;
    }
}

extern "C" void kernel_launch(void* const* d_in, const int* in_sizes, int n_in,
                              void* d_out, int out_size)
{
    const float* img = (const float*)d_in[0];   // (4,3,512,512) f32
    const float* psf = (const float*)d_in[1];   // (4,512,512)   f32
    float* out = (float*)d_out;                 // (4,3,512,512) f32

    dim3 block(32, 4, 1);
    dim3 grid(512 / 32, 512 / 32, 4);
    GaussPSF_kernel<<<grid, block>>>(img, psf, out);
}